// round 1
// baseline (speedup 1.0000x reference)
#include <cuda_runtime.h>
#include <math.h>
#include <stdint.h>

#define B_      16
#define T_      2048
#define F_      512
#define C_      256
#define NEG_    10
#define COPIES  11
#define STEPS_  12
#define U_      16          // u-tile per block in loss kernel
#define NPART   ((T_ / U_) * B_)   // 2048 partials

// Scratch (allocation-free rule: __device__ globals)
__device__ float g_tl[(size_t)B_ * T_ * C_];   // 32 MB: projected latents
__device__ float g_partials[NPART];

// ---------------------------------------------------------------------------
// Kernel A: tl = true_latent @ Wl + bl    (M=32768, N=256, K=512)
// Classic 128x128x8 SGEMM, 8x8 micro-tile, 256 threads.
// ---------------------------------------------------------------------------
__global__ void __launch_bounds__(256) gemm_tl_kernel(
    const float* __restrict__ A,     // [B*T, F] row-major
    const float* __restrict__ W,     // [F, C] row-major
    const float* __restrict__ bias)  // [C]
{
    const int K = F_, N = C_;
    __shared__ float As[8][128];
    __shared__ float Bs[8][128];

    int bx = blockIdx.x;             // N tile (0..1)
    int by = blockIdx.y;             // M tile (0..255)
    int tid = threadIdx.x;

    int arow = tid >> 1;             // 0..127
    int ac4  = (tid & 1) << 2;       // 0 or 4
    int brow = tid >> 5;             // 0..7
    int bc4  = (tid & 31) << 2;      // 0..124
    int tx = tid & 15, ty = tid >> 4;

    float acc[8][8];
#pragma unroll
    for (int i = 0; i < 8; i++)
#pragma unroll
        for (int j = 0; j < 8; j++) acc[i][j] = 0.f;

    const float* Ap = A + (size_t)(by * 128 + arow) * K + ac4;
    const float* Bp = W + (size_t)brow * N + bx * 128 + bc4;

    for (int k0 = 0; k0 < K; k0 += 8) {
        float4 a4 = *(const float4*)(Ap + k0);
        float4 b4 = *(const float4*)(Bp + (size_t)k0 * N);
        As[ac4 + 0][arow] = a4.x;
        As[ac4 + 1][arow] = a4.y;
        As[ac4 + 2][arow] = a4.z;
        As[ac4 + 3][arow] = a4.w;
        *(float4*)&Bs[brow][bc4] = b4;
        __syncthreads();

#pragma unroll
        for (int kk = 0; kk < 8; kk++) {
            float ar[8], br[8];
#pragma unroll
            for (int i = 0; i < 8; i++) ar[i] = As[kk][ty * 8 + i];
#pragma unroll
            for (int j = 0; j < 8; j++) br[j] = Bs[kk][tx * 8 + j];
#pragma unroll
            for (int i = 0; i < 8; i++)
#pragma unroll
                for (int j = 0; j < 8; j++)
                    acc[i][j] = fmaf(ar[i], br[j], acc[i][j]);
        }
        __syncthreads();
    }

    int col0 = bx * 128 + tx * 8;
    float bvals[8];
#pragma unroll
    for (int j = 0; j < 8; j++) bvals[j] = bias[col0 + j];

#pragma unroll
    for (int i = 0; i < 8; i++) {
        int row = by * 128 + ty * 8 + i;
        float4 v0, v1;
        v0.x = acc[i][0] + bvals[0];
        v0.y = acc[i][1] + bvals[1];
        v0.z = acc[i][2] + bvals[2];
        v0.w = acc[i][3] + bvals[3];
        v1.x = acc[i][4] + bvals[4];
        v1.y = acc[i][5] + bvals[5];
        v1.z = acc[i][6] + bvals[6];
        v1.w = acc[i][7] + bvals[7];
        *(float4*)&g_tl[(size_t)row * C_ + col0]     = v0;
        *(float4*)&g_tl[(size_t)row * C_ + col0 + 4] = v1;
    }
}

// ---------------------------------------------------------------------------
__device__ __forceinline__ float warp_sum(float v) {
#pragma unroll
    for (int o = 16; o; o >>= 1) v += __shfl_xor_sync(0xffffffffu, v, o);
    return v;
}

// ---------------------------------------------------------------------------
// Kernel B: fused dots + logits + logsumexp loss per (b, u-tile).
// For each u and copy c: target row r = (c==0 ? u : neg_idx[b,c-1,u]).
// logit(i) = Ws[i]*dot(ctx[b,u-i], tl[b,r]) + bs[i]*sum(tl[b,r]),  valid i<=u.
// Loss rows are (u, i): logsumexp over the 11 copies minus copy-0 logit.
// ---------------------------------------------------------------------------
__global__ void __launch_bounds__(256) loss_kernel(
    const float* __restrict__ ctx,   // [B, T, C]
    const float* __restrict__ Ws,    // [12]
    const float* __restrict__ bs,    // [12]
    const int*   __restrict__ neg)   // [B, NEG, T]
{
    __shared__ float ctx_s[(U_ + 11) * C_];           // 27 KB
    __shared__ float logits_s[U_ * STEPS_ * COPIES];  // 8.25 KB
    __shared__ float ws_s[STEPS_], bs_s[STEPS_];
    __shared__ float red_s[256];

    int b  = blockIdx.y;
    int u0 = blockIdx.x * U_;
    int tid = threadIdx.x;

    if (tid < STEPS_) { ws_s[tid] = Ws[tid]; bs_s[tid] = bs[tid]; }

    // Fill ctx tile rows [u0-11, u0+U): row j holds ctx[b, u0-11+j]; zero if OOB.
    const int NROWS = U_ + 11;
    for (int idx = tid; idx < NROWS * (C_ / 4); idx += 256) {
        int j  = idx / (C_ / 4);
        int c4 = (idx % (C_ / 4)) * 4;
        int gr = u0 - 11 + j;
        float4 v = make_float4(0.f, 0.f, 0.f, 0.f);
        if (gr >= 0)
            v = *(const float4*)(ctx + ((size_t)b * T_ + gr) * C_ + c4);
        *(float4*)&ctx_s[j * C_ + c4] = v;
    }
    __syncthreads();

    int warp = tid >> 5, lane = tid & 31;

    // 6 copy-pairs per u: (0,1)(2,3)(4,5)(6,7)(8,9)(10,-)
    for (int task = warp; task < U_ * 6; task += 8) {
        int ul = task / 6, pair = task % 6;
        int u  = u0 + ul;
        int c0 = pair * 2, c1 = c0 + 1;
        bool has1 = (c1 < COPIES);
        int r0 = (c0 == 0) ? u : neg[((size_t)b * NEG_ + (c0 - 1)) * T_ + u];
        int r1 = has1      ? neg[((size_t)b * NEG_ + (c1 - 1)) * T_ + u] : r0;

        const float* p0 = g_tl + ((size_t)b * T_ + r0) * C_ + lane;
        const float* p1 = g_tl + ((size_t)b * T_ + r1) * C_ + lane;

        float g0[8], g1[8], s0 = 0.f, s1 = 0.f;
#pragma unroll
        for (int k = 0; k < 8; k++) {
            g0[k] = p0[k * 32]; s0 += g0[k];
            g1[k] = p1[k * 32]; s1 += g1[k];
        }

        float a0[STEPS_], a1[STEPS_];
#pragma unroll
        for (int i = 0; i < STEPS_; i++) { a0[i] = 0.f; a1[i] = 0.f; }

#pragma unroll
        for (int i = 0; i < STEPS_; i++) {
            const float* cr = ctx_s + (ul + 11 - i) * C_ + lane;
#pragma unroll
            for (int k = 0; k < 8; k++) {
                float cf = cr[k * 32];
                a0[i] = fmaf(cf, g0[k], a0[i]);
                a1[i] = fmaf(cf, g1[k], a1[i]);
            }
        }

        s0 = warp_sum(s0);
        s1 = warp_sum(s1);
#pragma unroll
        for (int i = 0; i < STEPS_; i++) {
            a0[i] = warp_sum(a0[i]);
            a1[i] = warp_sum(a1[i]);
        }

        if (lane == 0) {
#pragma unroll
            for (int i = 0; i < STEPS_; i++) {
                logits_s[(ul * STEPS_ + i) * COPIES + c0] = ws_s[i] * a0[i] + bs_s[i] * s0;
                if (has1)
                    logits_s[(ul * STEPS_ + i) * COPIES + c1] = ws_s[i] * a1[i] + bs_s[i] * s1;
            }
        }
    }
    __syncthreads();

    // Loss rows: (u, i), valid when i <= u (t = u - i >= 0).
    float local = 0.f;
    for (int row = tid; row < U_ * STEPS_; row += 256) {
        int ul = row / STEPS_, i = row % STEPS_;
        int u = u0 + ul;
        if (i <= u) {
            const float* l = &logits_s[row * COPIES];
            float m = l[0];
#pragma unroll
            for (int c = 1; c < COPIES; c++) m = fmaxf(m, l[c]);
            float s = 0.f;
#pragma unroll
            for (int c = 0; c < COPIES; c++) s += expf(l[c] - m);
            local += m + logf(s) - l[0];
        }
    }

    red_s[tid] = local;
    __syncthreads();
    for (int off = 128; off; off >>= 1) {
        if (tid < off) red_s[tid] += red_s[tid + off];
        __syncthreads();
    }
    if (tid == 0)
        g_partials[blockIdx.y * (T_ / U_) + blockIdx.x] = red_s[0];
}

// ---------------------------------------------------------------------------
__global__ void __launch_bounds__(256) final_reduce_kernel(float* __restrict__ out) {
    __shared__ double red[256];
    int tid = threadIdx.x;
    double s = 0.0;
    for (int i = tid; i < NPART; i += 256) s += (double)g_partials[i];
    red[tid] = s;
    __syncthreads();
    for (int off = 128; off; off >>= 1) {
        if (tid < off) red[tid] += red[tid + off];
        __syncthreads();
    }
    if (tid == 0) out[0] = (float)red[0];
}

// ---------------------------------------------------------------------------
extern "C" void kernel_launch(void* const* d_in, const int* in_sizes, int n_in,
                              void* d_out, int out_size) {
    const float* true_latent = (const float*)d_in[0];   // [B,T,F]
    const float* ctx         = (const float*)d_in[1];   // [B,T,C]
    const float* Wl          = (const float*)d_in[2];   // [F,C]
    const float* bl          = (const float*)d_in[3];   // [C]
    const float* Ws          = (const float*)d_in[4];   // [12]
    const float* bs          = (const float*)d_in[5];   // [12]
    const int*   neg         = (const int*)d_in[6];     // [B,NEG,T]
    float* out = (float*)d_out;

    gemm_tl_kernel<<<dim3(C_ / 128, (B_ * T_) / 128), 256>>>(true_latent, Wl, bl);
    loss_kernel<<<dim3(T_ / U_, B_), 256>>>(ctx, Ws, bs, neg);
    final_reduce_kernel<<<1, 256>>>(out);
}

// round 2
// speedup vs baseline: 2.2243x; 2.2243x over previous
#include <cuda_runtime.h>
#include <math.h>
#include <stdint.h>
#include <mma.h>

using namespace nvcuda;

#define B_      16
#define T_      2048
#define F_      512
#define C_      256
#define NEG_    10
#define COPIES  11
#define STEPS_  12
#define U_      16
#define NPART   ((T_ / U_) * B_)

// Scratch (allocation-free rule: __device__ globals)
__device__ float g_tl[(size_t)B_ * T_ * C_];   // 32 MB projected latents
__device__ float g_partials[NPART];

// ---------------------------------------------------------------------------
// Kernel A: tl = true_latent @ Wl + bl  via TF32 tensor cores.
// M=32768, N=256, K=512. Block tile 128x128, KC=16 double-buffered.
// 8 warps in 4(m) x 2(n); each warp 32x64 = 2x4 wmma 16x16x8 tiles.
// ---------------------------------------------------------------------------
#define GKC   16
#define SB_LD 136   // 128 + 8 pad (multiple of 8 for wmma ldm)

__global__ void __launch_bounds__(256) gemm_tl_tc(
    const float* __restrict__ A,     // [B*T, F]
    const float* __restrict__ W,     // [F, C]
    const float* __restrict__ bias)  // [C]
{
    __shared__ float sA[2][128 * GKC];      // ld = 16
    __shared__ float sB[2][GKC * SB_LD];    // ld = 136
    __shared__ float epi[8][16 * 20];
    __shared__ float bias_s[128];

    const int tid  = threadIdx.x;
    const int bx   = blockIdx.x;   // N tile (0..1)
    const int by   = blockIdx.y;   // M tile (0..255)
    const int wid  = tid >> 5;
    const int lane = tid & 31;
    const int wm   = wid & 3;      // m sub-tile (32 rows)
    const int wn   = wid >> 2;     // n sub-tile (64 cols)

    if (tid < 128) bias_s[tid] = bias[bx * 128 + tid];

    wmma::fragment<wmma::accumulator, 16, 16, 8, float> acc[2][4];
#pragma unroll
    for (int i = 0; i < 2; i++)
#pragma unroll
        for (int j = 0; j < 4; j++) wmma::fill_fragment(acc[i][j], 0.f);

    // Per-thread tile load indices (2 float4 for A, 2 for B)
    int aidx0 = tid, aidx1 = tid + 256;
    int ar0 = aidx0 >> 2, ac0 = (aidx0 & 3) << 2;
    int ar1 = aidx1 >> 2, ac1 = (aidx1 & 3) << 2;
    int br0 = aidx0 >> 5, bc0 = (aidx0 & 31) << 2;
    int br1 = aidx1 >> 5, bc1 = (aidx1 & 31) << 2;

    const float* Abase = A + (size_t)(by * 128) * F_;
    const float* Wbase = W + bx * 128;

    float4 ra0, ra1, rb0, rb1;
    // preload tile 0
    ra0 = *(const float4*)(Abase + (size_t)ar0 * F_ + 0 + ac0);
    ra1 = *(const float4*)(Abase + (size_t)ar1 * F_ + 0 + ac1);
    rb0 = *(const float4*)(Wbase + (size_t)(0 + br0) * C_ + bc0);
    rb1 = *(const float4*)(Wbase + (size_t)(0 + br1) * C_ + bc1);
    *(float4*)&sA[0][ar0 * GKC + ac0] = ra0;
    *(float4*)&sA[0][ar1 * GKC + ac1] = ra1;
    *(float4*)&sB[0][br0 * SB_LD + bc0] = rb0;
    *(float4*)&sB[0][br1 * SB_LD + bc1] = rb1;
    __syncthreads();

    int buf = 0;
    const int NIT = F_ / GKC;   // 32
    for (int it = 0; it < NIT; ++it) {
        if (it + 1 < NIT) {
            int k0 = (it + 1) * GKC;
            ra0 = *(const float4*)(Abase + (size_t)ar0 * F_ + k0 + ac0);
            ra1 = *(const float4*)(Abase + (size_t)ar1 * F_ + k0 + ac1);
            rb0 = *(const float4*)(Wbase + (size_t)(k0 + br0) * C_ + bc0);
            rb1 = *(const float4*)(Wbase + (size_t)(k0 + br1) * C_ + bc1);
        }
#pragma unroll
        for (int ks = 0; ks < 2; ks++) {
            wmma::fragment<wmma::matrix_a, 16, 16, 8, wmma::precision::tf32, wmma::row_major> af[2];
            wmma::fragment<wmma::matrix_b, 16, 16, 8, wmma::precision::tf32, wmma::row_major> bf[4];
#pragma unroll
            for (int i = 0; i < 2; i++) {
                wmma::load_matrix_sync(af[i], &sA[buf][(wm * 32 + i * 16) * GKC + ks * 8], GKC);
#pragma unroll
                for (int e = 0; e < af[i].num_elements; e++)
                    af[i].x[e] = wmma::__float_to_tf32(af[i].x[e]);
            }
#pragma unroll
            for (int j = 0; j < 4; j++) {
                wmma::load_matrix_sync(bf[j], &sB[buf][(ks * 8) * SB_LD + wn * 64 + j * 16], SB_LD);
#pragma unroll
                for (int e = 0; e < bf[j].num_elements; e++)
                    bf[j].x[e] = wmma::__float_to_tf32(bf[j].x[e]);
            }
#pragma unroll
            for (int i = 0; i < 2; i++)
#pragma unroll
                for (int j = 0; j < 4; j++)
                    wmma::mma_sync(acc[i][j], af[i], bf[j], acc[i][j]);
        }
        if (it + 1 < NIT) {
            *(float4*)&sA[buf ^ 1][ar0 * GKC + ac0] = ra0;
            *(float4*)&sA[buf ^ 1][ar1 * GKC + ac1] = ra1;
            *(float4*)&sB[buf ^ 1][br0 * SB_LD + bc0] = rb0;
            *(float4*)&sB[buf ^ 1][br1 * SB_LD + bc1] = rb1;
        }
        __syncthreads();
        buf ^= 1;
    }

    // Epilogue: per-warp 16x16 smem bounce, add bias, float4 store.
    int row_l = lane >> 1;
    int col_l = (lane & 1) * 8;
#pragma unroll
    for (int i = 0; i < 2; i++) {
#pragma unroll
        for (int j = 0; j < 4; j++) {
            wmma::store_matrix_sync(&epi[wid][0], acc[i][j], 20, wmma::mem_row_major);
            __syncwarp();
            int grow = by * 128 + wm * 32 + i * 16 + row_l;
            int bl0  = wn * 64 + j * 16 + col_l;
            int gcol = bx * 128 + bl0;
            float4 o0, o1;
            const float* er = &epi[wid][row_l * 20 + col_l];
            o0.x = er[0] + bias_s[bl0 + 0];
            o0.y = er[1] + bias_s[bl0 + 1];
            o0.z = er[2] + bias_s[bl0 + 2];
            o0.w = er[3] + bias_s[bl0 + 3];
            o1.x = er[4] + bias_s[bl0 + 4];
            o1.y = er[5] + bias_s[bl0 + 5];
            o1.z = er[6] + bias_s[bl0 + 6];
            o1.w = er[7] + bias_s[bl0 + 7];
            *(float4*)&g_tl[(size_t)grow * C_ + gcol]     = o0;
            *(float4*)&g_tl[(size_t)grow * C_ + gcol + 4] = o1;
            __syncwarp();
        }
    }
}

// ---------------------------------------------------------------------------
__device__ __forceinline__ float dot8(float4 a, float4 b, float4 x, float4 y) {
    float s = a.x * x.x;
    s = fmaf(a.y, x.y, s);
    s = fmaf(a.z, x.z, s);
    s = fmaf(a.w, x.w, s);
    s = fmaf(b.x, y.x, s);
    s = fmaf(b.y, y.y, s);
    s = fmaf(b.z, y.z, s);
    s = fmaf(b.w, y.w, s);
    return s;
}

// ---------------------------------------------------------------------------
// Kernel B: fused dots + logits + logsumexp per (b, u-tile).
// 88 warp-tasks per block; each task: 2 target rows x (12 dots + rowsum),
// reduced with a folded 32-value butterfly (31 shfl; lane l ends with value l).
// ---------------------------------------------------------------------------
__global__ void __launch_bounds__(256) loss_kernel(
    const float* __restrict__ ctx,   // [B, T, C]
    const float* __restrict__ Ws,    // [12]
    const float* __restrict__ bs,    // [12]
    const int*   __restrict__ neg)   // [B, NEG, T]
{
    __shared__ float ctx_s[(U_ + 11) * C_];           // 27 KB
    __shared__ float logits_s[U_ * STEPS_ * COPIES];  // 8.25 KB
    __shared__ float ws_s[STEPS_], bs_s[STEPS_];
    __shared__ float red_s[256];

    const int b   = blockIdx.y;
    const int u0  = blockIdx.x * U_;
    const int tid = threadIdx.x;

    if (tid < STEPS_) { ws_s[tid] = Ws[tid]; bs_s[tid] = bs[tid]; }

    const int NROWS = U_ + 11;
    for (int idx = tid; idx < NROWS * (C_ / 4); idx += 256) {
        int j  = idx / (C_ / 4);
        int c4 = (idx % (C_ / 4)) * 4;
        int gr = u0 - 11 + j;
        float4 v = make_float4(0.f, 0.f, 0.f, 0.f);
        if (gr >= 0)
            v = *(const float4*)(ctx + ((size_t)b * T_ + gr) * C_ + c4);
        *(float4*)&ctx_s[j * C_ + c4] = v;
    }
    __syncthreads();

    const int warp = tid >> 5, lane = tid & 31;

    for (int task = warp; task < 88; task += 8) {
        int ul0, ul1, c0, c1;
        if (task < 80) {
            int q = task / 5, p = task % 5;
            ul0 = q; ul1 = q; c0 = 2 * p; c1 = 2 * p + 1;
        } else {
            int j = task - 80;
            ul0 = 2 * j; ul1 = 2 * j + 1; c0 = 10; c1 = 10;
        }
        int ug0 = u0 + ul0, ug1 = u0 + ul1;
        int r0 = (c0 == 0) ? ug0 : neg[((size_t)b * NEG_ + (c0 - 1)) * T_ + ug0];
        int r1 = neg[((size_t)b * NEG_ + (c1 - 1)) * T_ + ug1];

        // Gather target rows: lane covers elements [4l..4l+4) and [128+4l..)
        const float4* p0 = (const float4*)(g_tl + ((size_t)b * T_ + r0) * C_);
        const float4* p1 = (const float4*)(g_tl + ((size_t)b * T_ + r1) * C_);
        float4 g0a = p0[lane], g0b = p0[lane + 32];
        float4 g1a = p1[lane], g1b = p1[lane + 32];

        float v[32];
        v[12] = (g0a.x + g0a.y) + (g0a.z + g0a.w) + (g0b.x + g0b.y) + (g0b.z + g0b.w);
        v[28] = (g1a.x + g1a.y) + (g1a.z + g1a.w) + (g1b.x + g1b.y) + (g1b.z + g1b.w);
        v[13] = v[14] = v[15] = 0.f;
        v[29] = v[30] = v[31] = 0.f;

        bool same_u = (ul0 == ul1);
#pragma unroll
        for (int i = 0; i < STEPS_; i++) {
            const float4* cr0 = (const float4*)(ctx_s + (ul0 + 11 - i) * C_);
            float4 ca = cr0[lane], cb = cr0[lane + 32];
            v[i] = dot8(ca, cb, g0a, g0b);
            float4 da, db;
            if (same_u) { da = ca; db = cb; }
            else {
                const float4* cr1 = (const float4*)(ctx_s + (ul1 + 11 - i) * C_);
                da = cr1[lane]; db = cr1[lane + 32];
            }
            v[16 + i] = dot8(da, db, g1a, g1b);
        }

        // Folded reduction: 31 shfl; lane l ends with sum over lanes of v[l].
        const unsigned FULL = 0xffffffffu;
        float t16[16], t8[8], t4[4], t2[2], r;
#pragma unroll
        for (int j = 0; j < 16; j++) {
            float send = (lane & 16) ? v[j] : v[16 + j];
            float keep = (lane & 16) ? v[16 + j] : v[j];
            t16[j] = keep + __shfl_xor_sync(FULL, send, 16);
        }
#pragma unroll
        for (int j = 0; j < 8; j++) {
            float send = (lane & 8) ? t16[j] : t16[8 + j];
            float keep = (lane & 8) ? t16[8 + j] : t16[j];
            t8[j] = keep + __shfl_xor_sync(FULL, send, 8);
        }
#pragma unroll
        for (int j = 0; j < 4; j++) {
            float send = (lane & 4) ? t8[j] : t8[4 + j];
            float keep = (lane & 4) ? t8[4 + j] : t8[j];
            t4[j] = keep + __shfl_xor_sync(FULL, send, 4);
        }
#pragma unroll
        for (int j = 0; j < 2; j++) {
            float send = (lane & 2) ? t4[j] : t4[2 + j];
            float keep = (lane & 2) ? t4[2 + j] : t4[j];
            t2[j] = keep + __shfl_xor_sync(FULL, send, 2);
        }
        {
            float send = (lane & 1) ? t2[0] : t2[1];
            float keep = (lane & 1) ? t2[1] : t2[0];
            r = keep + __shfl_xor_sync(FULL, send, 1);
        }

        float s0t = __shfl_sync(FULL, r, 12);
        float s1t = __shfl_sync(FULL, r, 28);

        if (lane < 12) {
            logits_s[(ul0 * STEPS_ + lane) * COPIES + c0] =
                ws_s[lane] * r + bs_s[lane] * s0t;
        } else if (lane >= 16 && lane < 28) {
            int i = lane - 16;
            logits_s[(ul1 * STEPS_ + i) * COPIES + c1] =
                ws_s[i] * r + bs_s[i] * s1t;
        }
    }
    __syncthreads();

    // LSE rows: (u, i), valid when i <= u.
    float local = 0.f;
    for (int row = tid; row < U_ * STEPS_; row += 256) {
        int ul = row / STEPS_, i = row % STEPS_;
        int u = u0 + ul;
        if (i <= u) {
            const float* l = &logits_s[row * COPIES];
            float m = l[0];
#pragma unroll
            for (int c = 1; c < COPIES; c++) m = fmaxf(m, l[c]);
            float s = 0.f;
#pragma unroll
            for (int c = 0; c < COPIES; c++) s += expf(l[c] - m);
            local += m + logf(s) - l[0];
        }
    }

    red_s[tid] = local;
    __syncthreads();
    for (int off = 128; off; off >>= 1) {
        if (tid < off) red_s[tid] += red_s[tid + off];
        __syncthreads();
    }
    if (tid == 0)
        g_partials[blockIdx.y * (T_ / U_) + blockIdx.x] = red_s[0];
}

// ---------------------------------------------------------------------------
__global__ void __launch_bounds__(256) final_reduce_kernel(float* __restrict__ out) {
    __shared__ double red[256];
    int tid = threadIdx.x;
    double s = 0.0;
    for (int i = tid; i < NPART; i += 256) s += (double)g_partials[i];
    red[tid] = s;
    __syncthreads();
    for (int off = 128; off; off >>= 1) {
        if (tid < off) red[tid] += red[tid + off];
        __syncthreads();
    }
    if (tid == 0) out[0] = (float)red[0];
}

// ---------------------------------------------------------------------------
extern "C" void kernel_launch(void* const* d_in, const int* in_sizes, int n_in,
                              void* d_out, int out_size) {
    const float* true_latent = (const float*)d_in[0];   // [B,T,F]
    const float* ctx         = (const float*)d_in[1];   // [B,T,C]
    const float* Wl          = (const float*)d_in[2];   // [F,C]
    const float* bl          = (const float*)d_in[3];   // [C]
    const float* Ws          = (const float*)d_in[4];   // [12]
    const float* bs          = (const float*)d_in[5];   // [12]
    const int*   neg         = (const int*)d_in[6];     // [B,NEG,T]
    float* out = (float*)d_out;

    gemm_tl_tc<<<dim3(C_ / 128, (B_ * T_) / 128), 256>>>(true_latent, Wl, bl);
    loss_kernel<<<dim3(T_ / U_, B_), 256>>>(ctx, Ws, bs, neg);
    final_reduce_kernel<<<1, 256>>>(out);
}

// round 4
// speedup vs baseline: 2.6004x; 1.1691x over previous
#include <cuda_runtime.h>
#include <math.h>
#include <stdint.h>
#include <mma.h>

using namespace nvcuda;

#define B_      16
#define T_      2048
#define F_      512
#define C_      256
#define NEG_    10
#define COPIES  11
#define STEPS_  12
#define U_      16
#define NPART   ((T_ / U_) * B_)

// Scratch (allocation-free rule: __device__ globals)
__device__ float g_tl[(size_t)B_ * T_ * C_];   // 32 MB projected latents
__device__ float g_partials[NPART];

// ---------------------------------------------------------------------------
__device__ __forceinline__ uint32_t smem_u32(const void* p) {
    uint32_t a;
    asm("{ .reg .u64 t; cvta.to.shared.u64 t, %1; cvt.u32.u64 %0, t; }"
        : "=r"(a) : "l"(p));
    return a;
}
__device__ __forceinline__ void cp16(uint32_t dst, const void* src) {
    asm volatile("cp.async.cg.shared.global [%0], [%1], 16;"
                 :: "r"(dst), "l"(src) : "memory");
}
__device__ __forceinline__ void cp_commit() {
    asm volatile("cp.async.commit_group;" ::: "memory");
}
__device__ __forceinline__ void cp_wait1() {
    asm volatile("cp.async.wait_group 1;" ::: "memory");
}
__device__ __forceinline__ void cp_wait0() {
    asm volatile("cp.async.wait_group 0;" ::: "memory");
}

// ---------------------------------------------------------------------------
// Kernel A: tl = true_latent @ Wl + bl  via TF32 wmma tensor cores.
// M=32768, N=256, K=512. Block tile 128x128, KC=16, cp.async double buffer.
// 8 warps in 4(m) x 2(n); each warp 32x64 = 2x4 wmma 16x16x8 tiles.
// launch_bounds(256,2) -> <=128 regs -> 2 CTAs/SM.
// ---------------------------------------------------------------------------
#define GKC   16
#define SB_LD 136   // 128 + 8 pad

__global__ void __launch_bounds__(256, 2) gemm_tl_tc(
    const float* __restrict__ A,     // [B*T, F]
    const float* __restrict__ W,     // [F, C]
    const float* __restrict__ bias)  // [C]
{
    __shared__ float sA[2][128 * GKC];      // 16 KB
    __shared__ float sB[2][GKC * SB_LD];    // 17 KB
    __shared__ float epi[8][16 * 20];       // 10 KB
    __shared__ float bias_s[128];

    const int tid  = threadIdx.x;
    const int bx   = blockIdx.x;   // N tile (0..1)
    const int by   = blockIdx.y;   // M tile (0..255)
    const int wid  = tid >> 5;
    const int lane = tid & 31;
    const int wm   = wid & 3;      // m sub-tile (32 rows)
    const int wn   = wid >> 2;     // n sub-tile (64 cols)

    if (tid < 128) bias_s[tid] = bias[bx * 128 + tid];

    wmma::fragment<wmma::accumulator, 16, 16, 8, float> acc[2][4];
#pragma unroll
    for (int i = 0; i < 2; i++)
#pragma unroll
        for (int j = 0; j < 4; j++) wmma::fill_fragment(acc[i][j], 0.f);

    // Per-thread cp.async indices (2 float4 for A, 2 for B per tile)
    const int idx0 = tid, idx1 = tid + 256;
    const int ar0 = idx0 >> 2, ac0 = (idx0 & 3) << 2;
    const int ar1 = idx1 >> 2, ac1 = (idx1 & 3) << 2;
    const int br0 = idx0 >> 5, bc0 = (idx0 & 31) << 2;
    const int br1 = idx1 >> 5, bc1 = (idx1 & 31) << 2;

    const float* Abase = A + (size_t)(by * 128) * F_;
    const float* Wbase = W + bx * 128;

    const uint32_t sA0 = smem_u32(&sA[0][0]);
    const uint32_t sB0 = smem_u32(&sB[0][0]);
    const uint32_t dA0 = sA0 + (uint32_t)(ar0 * GKC + ac0) * 4u;
    const uint32_t dA1 = sA0 + (uint32_t)(ar1 * GKC + ac1) * 4u;
    const uint32_t dB0 = sB0 + (uint32_t)(br0 * SB_LD + bc0) * 4u;
    const uint32_t dB1 = sB0 + (uint32_t)(br1 * SB_LD + bc1) * 4u;
    const uint32_t bufA = sizeof(float) * 128 * GKC;
    const uint32_t bufB = sizeof(float) * GKC * SB_LD;

    auto issue_tile = [&](int k0, int buf) {
        uint32_t oA = buf ? bufA : 0u;
        uint32_t oB = buf ? bufB : 0u;
        cp16(dA0 + oA, Abase + (size_t)ar0 * F_ + k0 + ac0);
        cp16(dA1 + oA, Abase + (size_t)ar1 * F_ + k0 + ac1);
        cp16(dB0 + oB, Wbase + (size_t)(k0 + br0) * C_ + bc0);
        cp16(dB1 + oB, Wbase + (size_t)(k0 + br1) * C_ + bc1);
        cp_commit();
    };

    issue_tile(0, 0);

    const int NIT = F_ / GKC;   // 32
    int buf = 0;
    for (int it = 0; it < NIT; ++it) {
        if (it + 1 < NIT) {
            issue_tile((it + 1) * GKC, buf ^ 1);
            cp_wait1();
        } else {
            cp_wait0();
        }
        __syncthreads();

#pragma unroll
        for (int ks = 0; ks < 2; ks++) {
            wmma::fragment<wmma::matrix_a, 16, 16, 8, wmma::precision::tf32, wmma::row_major> af[2];
            wmma::fragment<wmma::matrix_b, 16, 16, 8, wmma::precision::tf32, wmma::row_major> bf[4];
#pragma unroll
            for (int i = 0; i < 2; i++) {
                wmma::load_matrix_sync(af[i], &sA[buf][(wm * 32 + i * 16) * GKC + ks * 8], GKC);
#pragma unroll
                for (int e = 0; e < af[i].num_elements; e++)
                    af[i].x[e] = wmma::__float_to_tf32(af[i].x[e]);
            }
#pragma unroll
            for (int j = 0; j < 4; j++) {
                wmma::load_matrix_sync(bf[j], &sB[buf][(ks * 8) * SB_LD + wn * 64 + j * 16], SB_LD);
#pragma unroll
                for (int e = 0; e < bf[j].num_elements; e++)
                    bf[j].x[e] = wmma::__float_to_tf32(bf[j].x[e]);
            }
#pragma unroll
            for (int i = 0; i < 2; i++)
#pragma unroll
                for (int j = 0; j < 4; j++)
                    wmma::mma_sync(acc[i][j], af[i], bf[j], acc[i][j]);
        }
        __syncthreads();
        buf ^= 1;
    }

    // Epilogue: per-warp 16x16 smem bounce, add bias, float4 store.
    const int row_l = lane >> 1;
    const int col_l = (lane & 1) * 8;
#pragma unroll
    for (int i = 0; i < 2; i++) {
#pragma unroll
        for (int j = 0; j < 4; j++) {
            wmma::store_matrix_sync(&epi[wid][0], acc[i][j], 20, wmma::mem_row_major);
            __syncwarp();
            int grow = by * 128 + wm * 32 + i * 16 + row_l;
            int bl0  = wn * 64 + j * 16 + col_l;
            int gcol = bx * 128 + bl0;
            float4 o0, o1;
            const float* er = &epi[wid][row_l * 20 + col_l];
            o0.x = er[0] + bias_s[bl0 + 0];
            o0.y = er[1] + bias_s[bl0 + 1];
            o0.z = er[2] + bias_s[bl0 + 2];
            o0.w = er[3] + bias_s[bl0 + 3];
            o1.x = er[4] + bias_s[bl0 + 4];
            o1.y = er[5] + bias_s[bl0 + 5];
            o1.z = er[6] + bias_s[bl0 + 6];
            o1.w = er[7] + bias_s[bl0 + 7];
            *(float4*)&g_tl[(size_t)grow * C_ + gcol]     = o0;
            *(float4*)&g_tl[(size_t)grow * C_ + gcol + 4] = o1;
            __syncwarp();
        }
    }
}

// ---------------------------------------------------------------------------
__device__ __forceinline__ float dot8(float4 a, float4 b, float4 x, float4 y) {
    float s = a.x * x.x;
    s = fmaf(a.y, x.y, s);
    s = fmaf(a.z, x.z, s);
    s = fmaf(a.w, x.w, s);
    s = fmaf(b.x, y.x, s);
    s = fmaf(b.y, y.y, s);
    s = fmaf(b.z, y.z, s);
    s = fmaf(b.w, y.w, s);
    return s;
}

// ---------------------------------------------------------------------------
// Kernel B: fused dots + logits + logsumexp per (b, u-tile). (unchanged)
// ---------------------------------------------------------------------------
__global__ void __launch_bounds__(256) loss_kernel(
    const float* __restrict__ ctx,   // [B, T, C]
    const float* __restrict__ Ws,    // [12]
    const float* __restrict__ bs,    // [12]
    const int*   __restrict__ neg)   // [B, NEG, T]
{
    __shared__ float ctx_s[(U_ + 11) * C_];
    __shared__ float logits_s[U_ * STEPS_ * COPIES];
    __shared__ float ws_s[STEPS_], bs_s[STEPS_];
    __shared__ float red_s[256];

    const int b   = blockIdx.y;
    const int u0  = blockIdx.x * U_;
    const int tid = threadIdx.x;

    if (tid < STEPS_) { ws_s[tid] = Ws[tid]; bs_s[tid] = bs[tid]; }

    const int NROWS = U_ + 11;
    for (int idx = tid; idx < NROWS * (C_ / 4); idx += 256) {
        int j  = idx / (C_ / 4);
        int c4 = (idx % (C_ / 4)) * 4;
        int gr = u0 - 11 + j;
        float4 v = make_float4(0.f, 0.f, 0.f, 0.f);
        if (gr >= 0)
            v = *(const float4*)(ctx + ((size_t)b * T_ + gr) * C_ + c4);
        *(float4*)&ctx_s[j * C_ + c4] = v;
    }
    __syncthreads();

    const int warp = tid >> 5, lane = tid & 31;

    for (int task = warp; task < 88; task += 8) {
        int ul0, ul1, c0, c1;
        if (task < 80) {
            int q = task / 5, p = task % 5;
            ul0 = q; ul1 = q; c0 = 2 * p; c1 = 2 * p + 1;
        } else {
            int j = task - 80;
            ul0 = 2 * j; ul1 = 2 * j + 1; c0 = 10; c1 = 10;
        }
        int ug0 = u0 + ul0, ug1 = u0 + ul1;
        int r0 = (c0 == 0) ? ug0 : neg[((size_t)b * NEG_ + (c0 - 1)) * T_ + ug0];
        int r1 = neg[((size_t)b * NEG_ + (c1 - 1)) * T_ + ug1];

        const float4* p0 = (const float4*)(g_tl + ((size_t)b * T_ + r0) * C_);
        const float4* p1 = (const float4*)(g_tl + ((size_t)b * T_ + r1) * C_);
        float4 g0a = p0[lane], g0b = p0[lane + 32];
        float4 g1a = p1[lane], g1b = p1[lane + 32];

        float v[32];
        v[12] = (g0a.x + g0a.y) + (g0a.z + g0a.w) + (g0b.x + g0b.y) + (g0b.z + g0b.w);
        v[28] = (g1a.x + g1a.y) + (g1a.z + g1a.w) + (g1b.x + g1b.y) + (g1b.z + g1b.w);
        v[13] = v[14] = v[15] = 0.f;
        v[29] = v[30] = v[31] = 0.f;

        bool same_u = (ul0 == ul1);
#pragma unroll
        for (int i = 0; i < STEPS_; i++) {
            const float4* cr0 = (const float4*)(ctx_s + (ul0 + 11 - i) * C_);
            float4 ca = cr0[lane], cb = cr0[lane + 32];
            v[i] = dot8(ca, cb, g0a, g0b);
            float4 da, db;
            if (same_u) { da = ca; db = cb; }
            else {
                const float4* cr1 = (const float4*)(ctx_s + (ul1 + 11 - i) * C_);
                da = cr1[lane]; db = cr1[lane + 32];
            }
            v[16 + i] = dot8(da, db, g1a, g1b);
        }

        const unsigned FULL = 0xffffffffu;
        float t16[16], t8[8], t4[4], t2[2], r;
#pragma unroll
        for (int j = 0; j < 16; j++) {
            float send = (lane & 16) ? v[j] : v[16 + j];
            float keep = (lane & 16) ? v[16 + j] : v[j];
            t16[j] = keep + __shfl_xor_sync(FULL, send, 16);
        }
#pragma unroll
        for (int j = 0; j < 8; j++) {
            float send = (lane & 8) ? t16[j] : t16[8 + j];
            float keep = (lane & 8) ? t16[8 + j] : t16[j];
            t8[j] = keep + __shfl_xor_sync(FULL, send, 8);
        }
#pragma unroll
        for (int j = 0; j < 4; j++) {
            float send = (lane & 4) ? t8[j] : t8[4 + j];
            float keep = (lane & 4) ? t8[4 + j] : t8[j];
            t4[j] = keep + __shfl_xor_sync(FULL, send, 4);
        }
#pragma unroll
        for (int j = 0; j < 2; j++) {
            float send = (lane & 2) ? t4[j] : t4[2 + j];
            float keep = (lane & 2) ? t4[2 + j] : t4[j];
            t2[j] = keep + __shfl_xor_sync(FULL, send, 2);
        }
        {
            float send = (lane & 1) ? t2[0] : t2[1];
            float keep = (lane & 1) ? t2[1] : t2[0];
            r = keep + __shfl_xor_sync(FULL, send, 1);
        }

        float s0t = __shfl_sync(FULL, r, 12);
        float s1t = __shfl_sync(FULL, r, 28);

        if (lane < 12) {
            logits_s[(ul0 * STEPS_ + lane) * COPIES + c0] =
                ws_s[lane] * r + bs_s[lane] * s0t;
        } else if (lane >= 16 && lane < 28) {
            int i = lane - 16;
            logits_s[(ul1 * STEPS_ + i) * COPIES + c1] =
                ws_s[i] * r + bs_s[i] * s1t;
        }
    }
    __syncthreads();

    float local = 0.f;
    for (int row = tid; row < U_ * STEPS_; row += 256) {
        int ul = row / STEPS_, i = row % STEPS_;
        int u = u0 + ul;
        if (i <= u) {
            const float* l = &logits_s[row * COPIES];
            float m = l[0];
#pragma unroll
            for (int c = 1; c < COPIES; c++) m = fmaxf(m, l[c]);
            float s = 0.f;
#pragma unroll
            for (int c = 0; c < COPIES; c++) s += expf(l[c] - m);
            local += m + logf(s) - l[0];
        }
    }

    red_s[tid] = local;
    __syncthreads();
    for (int off = 128; off; off >>= 1) {
        if (tid < off) red_s[tid] += red_s[tid + off];
        __syncthreads();
    }
    if (tid == 0)
        g_partials[blockIdx.y * (T_ / U_) + blockIdx.x] = red_s[0];
}

// ---------------------------------------------------------------------------
__global__ void __launch_bounds__(256) final_reduce_kernel(float* __restrict__ out) {
    __shared__ double red[256];
    int tid = threadIdx.x;
    double s = 0.0;
    for (int i = tid; i < NPART; i += 256) s += (double)g_partials[i];
    red[tid] = s;
    __syncthreads();
    for (int off = 128; off; off >>= 1) {
        if (tid < off) red[tid] += red[tid + off];
        __syncthreads();
    }
    if (tid == 0) out[0] = (float)red[0];
}

// ---------------------------------------------------------------------------
extern "C" void kernel_launch(void* const* d_in, const int* in_sizes, int n_in,
                              void* d_out, int out_size) {
    const float* true_latent = (const float*)d_in[0];   // [B,T,F]
    const float* ctx         = (const float*)d_in[1];   // [B,T,C]
    const float* Wl          = (const float*)d_in[2];   // [F,C]
    const float* bl          = (const float*)d_in[3];   // [C]
    const float* Ws          = (const float*)d_in[4];   // [12]
    const float* bs          = (const float*)d_in[5];   // [12]
    const int*   neg         = (const int*)d_in[6];     // [B,NEG,T]
    float* out = (float*)d_out;

    gemm_tl_tc<<<dim3(C_ / 128, (B_ * T_) / 128), 256>>>(true_latent, Wl, bl);
    loss_kernel<<<dim3(T_ / U_, B_), 256>>>(ctx, Ws, bs, neg);
    final_reduce_kernel<<<1, 256>>>(out);
}